// round 11
// baseline (speedup 1.0000x reference)
#include <cuda_runtime.h>
#include <cuda_bf16.h>

// Chamfer distance, B=16, N=M=2048, D=3 — shared-pair kernel v3.
// Each unique (pred,targ) d^2 evaluated once; row mins (pred->targ) and col
// mins (targ->pred) reduced from the same packed f32x2 values.
// v3 deltas: (1) preds staged PRE-PACKED in smem (kills 8 MOVs/warp-iter on
// the alu pipe), (2) both axes min the full d^2 value u, rows published with
// atomicMax like cols (no smem row tail), (3) finalize launched with PDL so
// its launch overhead overlaps main's tail.
// Cross-block combine: atomicMax on order-REVERSED float encoding (identity
// 0 => zero-init __device__ scratch; finalize decodes, sums, resets to 0 ->
// graph-replay safe).

#define CB_NPTS   2048
#define CB_B      16
#define CB_TPB    256
#define CB_NW     (CB_TPB / 32)           // 8 warps
#define CB_TI     64                      // preds per block
#define CB_ITILES (CB_NPTS / CB_TI)       // 32
#define CB_PPL    4                       // packed target-pairs per lane

__device__ unsigned g_col[CB_B * CB_NPTS];  // encR col minima; 0 = identity
__device__ unsigned g_row[CB_B * CB_NPTS];  // encR row minima; 0 = identity

__device__ __forceinline__ unsigned long long f32x2_fma(
    unsigned long long a, unsigned long long b, unsigned long long c) {
    unsigned long long d;
    asm("fma.rn.f32x2 %0, %1, %2, %3;" : "=l"(d) : "l"(a), "l"(b), "l"(c));
    return d;
}
__device__ __forceinline__ unsigned long long f32x2_add(
    unsigned long long a, unsigned long long b) {
    unsigned long long d;
    asm("add.rn.f32x2 %0, %1, %2;" : "=l"(d) : "l"(a), "l"(b));
    return d;
}
__device__ __forceinline__ void f32x2_unpack(unsigned long long v, float& lo, float& hi) {
    asm("mov.b64 {%0, %1}, %2;" : "=f"(lo), "=f"(hi) : "l"(v));
}
__device__ __forceinline__ unsigned long long f32x2_pack(float lo, float hi) {
    unsigned long long v;
    asm("mov.b64 %0, {%1, %2};" : "=l"(v) : "f"(lo), "f"(hi));
    return v;
}

// Order-PRESERVING encode: smaller float -> smaller code.
__device__ __forceinline__ unsigned encP(float f) {
    unsigned u = __float_as_uint(f);
    unsigned m = (unsigned)(((int)u) >> 31) | 0x80000000u;
    return u ^ m;
}
__device__ __forceinline__ float decP(unsigned e) {
    unsigned m = (~(unsigned)(((int)e) >> 31)) | 0x80000000u;
    return __uint_as_float(e ^ m);
}
// Order-REVERSED (atomicMax identity = 0): encR(finite) >= 1 always.
__device__ __forceinline__ unsigned encR(float f) { return ~encP(f); }
__device__ __forceinline__ float decR(unsigned r) { return decP(~r); }

__global__ __launch_bounds__(CB_TPB)
void chamfer_main(const float* __restrict__ preds,
                  const float* __restrict__ targs,
                  float* __restrict__ out)
{
    __shared__ ulonglong2 sPack[1024 * 2];   // targ pairs: {rax,ray},{rbx,rby} (32KB)
    __shared__ ulonglong2 sQa[CB_TI];        // { pack(x0,x0), pack(x1,x1) }
    __shared__ ulonglong2 sQb[CB_TI];        // { pack(x2,x2), pack(xx,xx) }

    const int b   = blockIdx.y;
    const int tid = threadIdx.x;
    const int wid = tid >> 5;
    const int ln  = tid & 31;

    if (blockIdx.x == 0 && blockIdx.y == 0 && tid == 0)
        out[0] = 0.0f;    // visible to finalize via PDL grid-dependency sync

    // ---- stage ALL 2048 targets as packed, pre-scaled pairs ----
    const float* tB = targs + (size_t)b * CB_NPTS * 3;
    for (int pp = tid; pp < 1024; pp += CB_TPB) {
        const float* r = tB + pp * 6;
        float a0 = r[0], a1 = r[1], a2 = r[2];
        float c0 = r[3], c1 = r[4], c2 = r[5];
        sPack[2 * pp]     = make_ulonglong2(f32x2_pack(-2.0f * a0, -2.0f * c0),
                                            f32x2_pack(-2.0f * a1, -2.0f * c1));
        sPack[2 * pp + 1] = make_ulonglong2(f32x2_pack(-2.0f * a2, -2.0f * c2),
                                            f32x2_pack(fmaf(a0, a0, fmaf(a1, a1, a2 * a2)),
                                                       fmaf(c0, c0, fmaf(c1, c1, c2 * c2))));
    }
    // ---- stage this block's 64 preds PRE-PACKED with |x|^2 ----
    const float* pB = preds + (size_t)b * CB_NPTS * 3;
    if (tid < CB_TI) {
        int i = blockIdx.x * CB_TI + tid;
        float x0 = pB[i * 3 + 0];
        float x1 = pB[i * 3 + 1];
        float x2 = pB[i * 3 + 2];
        float xx = fmaf(x0, x0, fmaf(x1, x1, x2 * x2));
        sQa[tid] = make_ulonglong2(f32x2_pack(x0, x0), f32x2_pack(x1, x1));
        sQb[tid] = make_ulonglong2(f32x2_pack(x2, x2), f32x2_pack(xx, xx));
    }
    __syncthreads();

    // ---- this lane's 4 packed target pairs in registers ----
    unsigned long long rax[CB_PPL], ray[CB_PPL], rbx[CB_PPL], rby[CB_PPL];
    #pragma unroll
    for (int r = 0; r < CB_PPL; ++r) {
        int pp = wid * (32 * CB_PPL) + r * 32 + ln;
        ulonglong2 pa = sPack[2 * pp];
        ulonglong2 pb = sPack[2 * pp + 1];
        rax[r] = pa.x;  ray[r] = pa.y;
        rbx[r] = pb.x;  rby[r] = pb.y;
    }

    float cmin[2 * CB_PPL];
    #pragma unroll
    for (int r = 0; r < 2 * CB_PPL; ++r) cmin[r] = 3.402823466e38f;

    unsigned* grow = g_row + (size_t)b * CB_NPTS + blockIdx.x * CB_TI;

    // ---- main loop: 64 preds x 8 lane-targets ----
    for (int i = 0; i < CB_TI; ++i) {
        ulonglong2 qa = sQa[i];    // LDS.128 broadcast: {q0, q1}
        ulonglong2 qb = sQb[i];    // LDS.128 broadcast: {q2, xx}

        float rm0 = 3.402823466e38f, rm1 = 3.402823466e38f;
        #pragma unroll
        for (int r = 0; r < CB_PPL; ++r) {
            unsigned long long t = f32x2_fma(qb.x, rbx[r], rby[r]);
            t = f32x2_fma(qa.y, ray[r], t);
            t = f32x2_fma(qa.x, rax[r], t);            // yy - 2 x.y
            unsigned long long u = f32x2_add(t, qb.y); // full d^2 (2 targs)
            float ul, uh;
            f32x2_unpack(u, ul, uh);                   // free register alias
            rm0 = fminf(rm0, ul);
            rm1 = fminf(rm1, uh);
            cmin[2 * r]     = fminf(cmin[2 * r],     ul);
            cmin[2 * r + 1] = fminf(cmin[2 * r + 1], uh);
        }
        unsigned e = __reduce_min_sync(0xffffffffu, encP(fminf(rm0, rm1)));
        if (ln == 0) atomicMax(&grow[i], ~e);          // encR = ~encP
    }

    // ---- publish col minima (REDG.MAX on reversed encoding) ----
    unsigned* gc = g_col + (size_t)b * CB_NPTS;
    #pragma unroll
    for (int r = 0; r < CB_PPL; ++r) {
        int pp = wid * (32 * CB_PPL) + r * 32 + ln;
        atomicMax(&gc[2 * pp],     encR(cmin[2 * r]));
        atomicMax(&gc[2 * pp + 1], encR(cmin[2 * r + 1]));
    }

    cudaTriggerProgrammaticLaunchCompletion();
}

__global__ __launch_bounds__(256)
void chamfer_finalize(float* __restrict__ out)
{
    cudaGridDependencySynchronize();    // wait for chamfer_main completion

    __shared__ float sRed[8];
    const int idx = blockIdx.x * 256 + threadIdx.x;   // [0, 32768)

    float acc = decR(g_col[idx]) + decR(g_row[idx]);
    g_col[idx] = 0u;                    // reset identities for next replay
    g_row[idx] = 0u;

    #pragma unroll
    for (int o = 16; o > 0; o >>= 1)
        acc += __shfl_down_sync(0xffffffffu, acc, o);
    if ((threadIdx.x & 31) == 0) sRed[threadIdx.x >> 5] = acc;
    __syncthreads();
    if (threadIdx.x < 32) {
        float v2 = (threadIdx.x < 8) ? sRed[threadIdx.x] : 0.0f;
        #pragma unroll
        for (int o = 4; o > 0; o >>= 1)
            v2 += __shfl_down_sync(0xffffffffu, v2, o);
        if (threadIdx.x == 0) atomicAdd(out, v2);
    }
}

extern "C" void kernel_launch(void* const* d_in, const int* in_sizes, int n_in,
                              void* d_out, int out_size) {
    const float* preds = (const float*)d_in[0];
    const float* targs = (const float*)d_in[1];
    float* out = (float*)d_out;

    dim3 gridM(CB_ITILES, CB_B);        // (32, 16) = 512 blocks x 256 thr
    chamfer_main<<<gridM, CB_TPB>>>(preds, targs, out);

    // Finalize with Programmatic Dependent Launch: launch overlaps main's
    // tail; cudaGridDependencySynchronize() inside provides ordering.
    cudaLaunchConfig_t cfg = {};
    cfg.gridDim  = dim3((CB_B * CB_NPTS) / 256);   // 128 blocks
    cfg.blockDim = dim3(256);
    cudaLaunchAttribute attrs[1];
    attrs[0].id = cudaLaunchAttributeProgrammaticStreamSerialization;
    attrs[0].val.programmaticStreamSerializationAllowed = 1;
    cfg.attrs = attrs;
    cfg.numAttrs = 1;
    cudaLaunchKernelEx(&cfg, chamfer_finalize, out);
}

// round 12
// speedup vs baseline: 1.0702x; 1.0702x over previous
#include <cuda_runtime.h>
#include <cuda_bf16.h>

// Chamfer distance, B=16, N=M=2048, D=3 — shared-pair kernel v2b.
// EXACTLY R10 (best: 25.1us) plus ONE change: preds staged PRE-PACKED in
// smem (two ulonglong2 per pred), removing 8 broadcast MOVs per (i,warp)
// from the alu pipe in exchange for 1 extra LDS.128 broadcast.
//
// Each unique (pred,targ) d^2 evaluated once; row mins (pred->targ) and col
// mins (targ->pred) reduced from the same packed f32x2 values.
// Rows: REDUX.MIN.U32 per warp -> smem -> block combine -> atomicAdd(g_rowsum).
// Cols: register mins -> atomicMax on order-REVERSED encoding (identity 0 =>
// zero-init scratch, reset by finalize -> graph-replay safe).

#define CB_NPTS   2048
#define CB_B      16
#define CB_TPB    256
#define CB_NW     (CB_TPB / 32)           // 8 warps
#define CB_TI     64                      // preds per block
#define CB_ITILES (CB_NPTS / CB_TI)       // 32
#define CB_PPL    4                       // packed target-pairs per lane

__device__ unsigned g_col[CB_B * CB_NPTS];  // encR col minima; 0 = identity
__device__ float    g_rowsum;               // zero-init; reset by finalize

__device__ __forceinline__ unsigned long long f32x2_fma(
    unsigned long long a, unsigned long long b, unsigned long long c) {
    unsigned long long d;
    asm("fma.rn.f32x2 %0, %1, %2, %3;" : "=l"(d) : "l"(a), "l"(b), "l"(c));
    return d;
}
__device__ __forceinline__ unsigned long long f32x2_add(
    unsigned long long a, unsigned long long b) {
    unsigned long long d;
    asm("add.rn.f32x2 %0, %1, %2;" : "=l"(d) : "l"(a), "l"(b));
    return d;
}
__device__ __forceinline__ void f32x2_unpack(unsigned long long v, float& lo, float& hi) {
    asm("mov.b64 {%0, %1}, %2;" : "=f"(lo), "=f"(hi) : "l"(v));
}
__device__ __forceinline__ unsigned long long f32x2_pack(float lo, float hi) {
    unsigned long long v;
    asm("mov.b64 %0, {%1, %2};" : "=l"(v) : "f"(lo), "f"(hi));
    return v;
}

// Order-PRESERVING encode (for REDUX.MIN): smaller float -> smaller code.
__device__ __forceinline__ unsigned encP(float f) {
    unsigned u = __float_as_uint(f);
    unsigned m = (unsigned)(((int)u) >> 31) | 0x80000000u;
    return u ^ m;
}
__device__ __forceinline__ float decP(unsigned e) {
    unsigned m = (~(unsigned)(((int)e) >> 31)) | 0x80000000u;
    return __uint_as_float(e ^ m);
}
// Order-REVERSED encode (for atomicMax with zero identity).
__device__ __forceinline__ unsigned encR(float f) { return ~encP(f); }
__device__ __forceinline__ float decR(unsigned r) { return decP(~r); }

__global__ __launch_bounds__(CB_TPB)
void chamfer_main(const float* __restrict__ preds,
                  const float* __restrict__ targs,
                  float* __restrict__ out)
{
    __shared__ ulonglong2 sPack[1024 * 2];   // targ pairs (32KB)
    __shared__ ulonglong2 sQa[CB_TI];        // { pack(x0,x0), pack(x1,x1) }
    __shared__ ulonglong2 sQb[CB_TI];        // { pack(x2,x2), pack(xx,xx) }
    __shared__ float      sXX[CB_TI];        // |x|^2 scalar (row tail)
    __shared__ unsigned   sRowE[CB_TI * CB_NW];  // per-warp encoded row mins

    const int b   = blockIdx.y;
    const int tid = threadIdx.x;
    const int wid = tid >> 5;
    const int ln  = tid & 31;

    if (blockIdx.x == 0 && blockIdx.y == 0 && tid == 0)
        out[0] = 0.0f;    // finalize runs after us in stream order

    // ---- stage ALL 2048 targets as packed, pre-scaled pairs ----
    const float* tB = targs + (size_t)b * CB_NPTS * 3;
    for (int pp = tid; pp < 1024; pp += CB_TPB) {
        const float* r = tB + pp * 6;
        float a0 = r[0], a1 = r[1], a2 = r[2];
        float c0 = r[3], c1 = r[4], c2 = r[5];
        sPack[2 * pp]     = make_ulonglong2(f32x2_pack(-2.0f * a0, -2.0f * c0),
                                            f32x2_pack(-2.0f * a1, -2.0f * c1));
        sPack[2 * pp + 1] = make_ulonglong2(f32x2_pack(-2.0f * a2, -2.0f * c2),
                                            f32x2_pack(fmaf(a0, a0, fmaf(a1, a1, a2 * a2)),
                                                       fmaf(c0, c0, fmaf(c1, c1, c2 * c2))));
    }
    // ---- stage this block's 64 preds PRE-PACKED with |x|^2 ----
    const float* pB = preds + (size_t)b * CB_NPTS * 3;
    if (tid < CB_TI) {
        int i = blockIdx.x * CB_TI + tid;
        float x0 = pB[i * 3 + 0];
        float x1 = pB[i * 3 + 1];
        float x2 = pB[i * 3 + 2];
        float xx = fmaf(x0, x0, fmaf(x1, x1, x2 * x2));
        sQa[tid] = make_ulonglong2(f32x2_pack(x0, x0), f32x2_pack(x1, x1));
        sQb[tid] = make_ulonglong2(f32x2_pack(x2, x2), f32x2_pack(xx, xx));
        sXX[tid] = xx;
    }
    __syncthreads();

    // ---- pull this lane's 4 packed target pairs into registers ----
    unsigned long long rax[CB_PPL], ray[CB_PPL], rbx[CB_PPL], rby[CB_PPL];
    #pragma unroll
    for (int r = 0; r < CB_PPL; ++r) {
        int pp = wid * (32 * CB_PPL) + r * 32 + ln;
        ulonglong2 pa = sPack[2 * pp];
        ulonglong2 pb = sPack[2 * pp + 1];
        rax[r] = pa.x;  ray[r] = pa.y;
        rbx[r] = pb.x;  rby[r] = pb.y;
    }

    float cmin[2 * CB_PPL];
    #pragma unroll
    for (int r = 0; r < 2 * CB_PPL; ++r) cmin[r] = 3.402823466e38f;

    // ---- main loop: 64 preds x 8 lane-targets ----
    for (int i = 0; i < CB_TI; ++i) {
        ulonglong2 qa = sQa[i];    // LDS.128 broadcast: {q0, q1}
        ulonglong2 qb = sQb[i];    // LDS.128 broadcast: {q2, xx}

        float rm0 = 3.402823466e38f, rm1 = 3.402823466e38f;
        #pragma unroll
        for (int r = 0; r < CB_PPL; ++r) {
            unsigned long long t = f32x2_fma(qb.x, rbx[r], rby[r]);
            t = f32x2_fma(qa.y, ray[r], t);
            t = f32x2_fma(qa.x, rax[r], t);            // t = yy - 2 x.y
            unsigned long long u = f32x2_add(t, qb.y); // u = full d^2
            float ul, uh;
            f32x2_unpack(u, ul, uh);                   // free register alias
            rm0 = fminf(rm0, ul);
            rm1 = fminf(rm1, uh);
            cmin[2 * r]     = fminf(cmin[2 * r],     ul);
            cmin[2 * r + 1] = fminf(cmin[2 * r + 1], uh);
        }
        // row min of d^2 (xx constant over j: subtract later not needed --
        // we sum min d^2 directly, matching reference numerics via decode)
        unsigned e = encP(fminf(rm0, rm1));
        e = __reduce_min_sync(0xffffffffu, e);          // REDUX.MIN.U32
        if (ln == 0) sRowE[i * CB_NW + wid] = e;
    }

    // ---- publish col minima (REDG.MAX on reversed encoding) ----
    unsigned* gc = g_col + (size_t)b * CB_NPTS;
    #pragma unroll
    for (int r = 0; r < CB_PPL; ++r) {
        int pp = wid * (32 * CB_PPL) + r * 32 + ln;
        atomicMax(&gc[2 * pp],     encR(cmin[2 * r]));
        atomicMax(&gc[2 * pp + 1], encR(cmin[2 * r + 1]));
    }

    __syncthreads();

    // ---- row side: combine 8 warps, sum, one atomic per warp ----
    if (tid < CB_TI) {
        const unsigned* e = &sRowE[tid * CB_NW];
        unsigned m01 = min(e[0], e[1]), m23 = min(e[2], e[3]);
        unsigned m45 = min(e[4], e[5]), m67 = min(e[6], e[7]);
        unsigned em = min(min(m01, m23), min(m45, m67));
        float val = decP(em);          // already full d^2 (includes xx)
        #pragma unroll
        for (int o = 16; o > 0; o >>= 1)
            val += __shfl_down_sync(0xffffffffu, val, o);
        if (ln == 0) atomicAdd(&g_rowsum, val);
    }
}

__global__ __launch_bounds__(128)
void chamfer_finalize(float* __restrict__ out)
{
    __shared__ float sRed[4];
    const int b = blockIdx.y;
    const int j = blockIdx.x * 128 + threadIdx.x;   // 16 blocks per batch
    unsigned* gc = g_col + (size_t)b * CB_NPTS;

    float acc = decR(gc[j]);
    gc[j] = 0u;                          // reset identity for next replay

    #pragma unroll
    for (int o = 16; o > 0; o >>= 1)
        acc += __shfl_down_sync(0xffffffffu, acc, o);
    if ((threadIdx.x & 31) == 0) sRed[threadIdx.x >> 5] = acc;
    __syncthreads();
    if (threadIdx.x == 0) {
        float v2 = sRed[0] + sRed[1] + sRed[2] + sRed[3];
        if (blockIdx.x == 0 && blockIdx.y == 0) {
            v2 += g_rowsum;              // consume row-side sum
            g_rowsum = 0.0f;             // reset for next replay
        }
        atomicAdd(out, v2);
    }
}

extern "C" void kernel_launch(void* const* d_in, const int* in_sizes, int n_in,
                              void* d_out, int out_size) {
    const float* preds = (const float*)d_in[0];
    const float* targs = (const float*)d_in[1];
    float* out = (float*)d_out;

    dim3 gridM(CB_ITILES, CB_B);        // (32, 16) = 512 blocks x 256 thr
    chamfer_main<<<gridM, CB_TPB>>>(preds, targs, out);

    dim3 gridF(CB_NPTS / 128, CB_B);    // (16, 16) = 256 blocks x 128 thr
    chamfer_finalize<<<gridF, 128>>>(out);
}

// round 13
// speedup vs baseline: 1.1509x; 1.0755x over previous
#include <cuda_runtime.h>
#include <cuda_bf16.h>

// Chamfer distance, B=16, N=M=2048, D=3 — shared-pair kernel v4.
// Hot loop is EXACTLY R10's (best measured: 25.1us total) — float4 query
// staging, rm minned on t (= yy - 2 x.y), cols minned on u (= full d^2).
// ONE change vs R10: the finalize KERNEL is replaced by an in-kernel
// per-batch election tail (ticket on g_cnt[b]; 32nd block of the batch sums
// + resets its 2048 col words; 16th batch winner writes out[0] = rowsum +
// sum of per-batch col sums and resets all globals -> graph-replay safe).

#define CB_NPTS   2048
#define CB_B      16
#define CB_TPB    256
#define CB_NW     (CB_TPB / 32)           // 8 warps
#define CB_TI     64                      // preds per block
#define CB_ITILES (CB_NPTS / CB_TI)       // 32
#define CB_PPL    4                       // packed target-pairs per lane

__device__ unsigned g_col[CB_B * CB_NPTS];  // encR col minima; 0 = identity
__device__ float    g_rowsum;               // zero-init; reset by grand winner
__device__ float    g_sum[CB_B];            // per-batch col sums
__device__ unsigned g_cnt[CB_B];            // zero-init; reset by batch winner
__device__ unsigned g_cnt2;                 // zero-init; reset by grand winner

__device__ __forceinline__ unsigned long long f32x2_fma(
    unsigned long long a, unsigned long long b, unsigned long long c) {
    unsigned long long d;
    asm("fma.rn.f32x2 %0, %1, %2, %3;" : "=l"(d) : "l"(a), "l"(b), "l"(c));
    return d;
}
__device__ __forceinline__ unsigned long long f32x2_add(
    unsigned long long a, unsigned long long b) {
    unsigned long long d;
    asm("add.rn.f32x2 %0, %1, %2;" : "=l"(d) : "l"(a), "l"(b));
    return d;
}
__device__ __forceinline__ void f32x2_unpack(unsigned long long v, float& lo, float& hi) {
    asm("mov.b64 {%0, %1}, %2;" : "=f"(lo), "=f"(hi) : "l"(v));
}
__device__ __forceinline__ unsigned long long f32x2_pack(float lo, float hi) {
    unsigned long long v;
    asm("mov.b64 %0, {%1, %2};" : "=l"(v) : "f"(lo), "f"(hi));
    return v;
}

// Order-PRESERVING encode (for REDUX.MIN): smaller float -> smaller code.
__device__ __forceinline__ unsigned encP(float f) {
    unsigned u = __float_as_uint(f);
    unsigned m = (unsigned)(((int)u) >> 31) | 0x80000000u;
    return u ^ m;
}
__device__ __forceinline__ float decP(unsigned e) {
    unsigned m = (~(unsigned)(((int)e) >> 31)) | 0x80000000u;
    return __uint_as_float(e ^ m);
}
// Order-REVERSED encode (for atomicMax with zero identity).
__device__ __forceinline__ unsigned encR(float f) { return ~encP(f); }
__device__ __forceinline__ float decR(unsigned r) { return decP(~r); }

__global__ __launch_bounds__(CB_TPB)
void chamfer_main(const float* __restrict__ preds,
                  const float* __restrict__ targs,
                  float* __restrict__ out)
{
    __shared__ unsigned long long sPack[1024 * 4];  // packed targ pairs (32KB)
    __shared__ float4   sQ[CB_TI];                  // (x0,x1,x2,|x|^2)
    __shared__ unsigned sRowE[CB_TI * CB_NW];       // per-warp encoded row mins
    __shared__ unsigned sTicket;
    __shared__ float    sRed[CB_NW];

    const int b   = blockIdx.y;
    const int tid = threadIdx.x;
    const int wid = tid >> 5;
    const int ln  = tid & 31;

    // ---- stage ALL 2048 targets as packed, pre-scaled pairs ----
    const float* tB = targs + (size_t)b * CB_NPTS * 3;
    for (int pp = tid; pp < 1024; pp += CB_TPB) {
        const float* r = tB + pp * 6;
        float a0 = r[0], a1 = r[1], a2 = r[2];
        float c0 = r[3], c1 = r[4], c2 = r[5];
        sPack[pp * 4 + 0] = f32x2_pack(-2.0f * a0, -2.0f * c0);
        sPack[pp * 4 + 1] = f32x2_pack(-2.0f * a1, -2.0f * c1);
        sPack[pp * 4 + 2] = f32x2_pack(-2.0f * a2, -2.0f * c2);
        sPack[pp * 4 + 3] = f32x2_pack(fmaf(a0, a0, fmaf(a1, a1, a2 * a2)),
                                       fmaf(c0, c0, fmaf(c1, c1, c2 * c2)));
    }
    // ---- stage this block's 64 preds with |x|^2 ----
    const float* pB = preds + (size_t)b * CB_NPTS * 3;
    if (tid < CB_TI) {
        int i = blockIdx.x * CB_TI + tid;
        float x0 = pB[i * 3 + 0];
        float x1 = pB[i * 3 + 1];
        float x2 = pB[i * 3 + 2];
        sQ[tid] = make_float4(x0, x1, x2, fmaf(x0, x0, fmaf(x1, x1, x2 * x2)));
    }
    __syncthreads();

    // ---- pull this lane's 4 packed target pairs into registers ----
    unsigned long long rax[CB_PPL], ray[CB_PPL], rbx[CB_PPL], rby[CB_PPL];
    #pragma unroll
    for (int r = 0; r < CB_PPL; ++r) {
        int pp = wid * (32 * CB_PPL) + r * 32 + ln;
        rax[r] = sPack[pp * 4 + 0];
        ray[r] = sPack[pp * 4 + 1];
        rbx[r] = sPack[pp * 4 + 2];
        rby[r] = sPack[pp * 4 + 3];
    }

    float cmin[2 * CB_PPL];
    #pragma unroll
    for (int r = 0; r < 2 * CB_PPL; ++r) cmin[r] = 3.402823466e38f;

    // ---- main loop: 64 preds x 8 lane-targets (EXACT R10 body) ----
    for (int i = 0; i < CB_TI; ++i) {
        float4 q = sQ[i];                                   // LDS.128 broadcast
        unsigned long long q0  = f32x2_pack(q.x, q.x);
        unsigned long long q1  = f32x2_pack(q.y, q.y);
        unsigned long long q2  = f32x2_pack(q.z, q.z);
        unsigned long long xxp = f32x2_pack(q.w, q.w);

        float rm0 = 3.402823466e38f, rm1 = 3.402823466e38f;
        #pragma unroll
        for (int r = 0; r < CB_PPL; ++r) {
            unsigned long long t = f32x2_fma(q2, rbx[r], rby[r]);
            t = f32x2_fma(q1, ray[r], t);
            t = f32x2_fma(q0, rax[r], t);               // t = yy - 2 x.y
            unsigned long long u = f32x2_add(t, xxp);   // u = d^2
            float tl, th, ul, uh;
            f32x2_unpack(t, tl, th);
            f32x2_unpack(u, ul, uh);
            rm0 = fminf(rm0, tl);
            rm1 = fminf(rm1, th);
            cmin[2 * r]     = fminf(cmin[2 * r],     ul);
            cmin[2 * r + 1] = fminf(cmin[2 * r + 1], uh);
        }
        unsigned e = encP(fminf(rm0, rm1));
        e = __reduce_min_sync(0xffffffffu, e);          // REDUX.MIN.U32
        if (ln == 0) sRowE[i * CB_NW + wid] = e;
    }

    // ---- publish col minima (REDG.MAX on reversed encoding) ----
    unsigned* gc = g_col + (size_t)b * CB_NPTS;
    #pragma unroll
    for (int r = 0; r < CB_PPL; ++r) {
        int pp = wid * (32 * CB_PPL) + r * 32 + ln;
        atomicMax(&gc[2 * pp],     encR(cmin[2 * r]));
        atomicMax(&gc[2 * pp + 1], encR(cmin[2 * r + 1]));
    }

    __syncthreads();

    // ---- row side: combine 8 warps, add |x|^2, sum, one atomic per warp ----
    if (tid < CB_TI) {
        const unsigned* e = &sRowE[tid * CB_NW];
        unsigned m01 = min(e[0], e[1]), m23 = min(e[2], e[3]);
        unsigned m45 = min(e[4], e[5]), m67 = min(e[6], e[7]);
        unsigned em = min(min(m01, m23), min(m45, m67));
        float val = sQ[tid].w + decP(em);
        #pragma unroll
        for (int o = 16; o > 0; o >>= 1)
            val += __shfl_down_sync(0xffffffffu, val, o);
        if (ln == 0) atomicAdd(&g_rowsum, val);
    }

    // ---- election tail: 32nd block of this batch sums the col side ----
    __threadfence();   // order our REDGs/atomicAdds before the ticket
    __syncthreads();
    if (tid == 0) sTicket = atomicAdd(&g_cnt[b], 1u);
    __syncthreads();
    if (sTicket != CB_ITILES - 1) return;

    __threadfence();   // acquire: all batch-b blocks' REDGs visible
    float acc = 0.0f;
    #pragma unroll
    for (int k = 0; k < CB_NPTS / CB_TPB; ++k) {
        int j = k * CB_TPB + tid;
        acc += decR(gc[j]);
        gc[j] = 0u;                        // reset identity for next replay
    }
    #pragma unroll
    for (int o = 16; o > 0; o >>= 1)
        acc += __shfl_down_sync(0xffffffffu, acc, o);
    if (ln == 0) sRed[wid] = acc;
    __syncthreads();

    if (tid == 0) {
        float v = 0.0f;
        #pragma unroll
        for (int w = 0; w < CB_NW; ++w) v += sRed[w];
        g_sum[b] = v;
        g_cnt[b] = 0u;                     // reset for next replay
        __threadfence();
        unsigned t2 = atomicAdd(&g_cnt2, 1u);
        if (t2 == CB_B - 1) {              // grand winner: all batches done
            __threadfence();
            float s = g_rowsum;
            #pragma unroll
            for (int i = 0; i < CB_B; ++i) s += g_sum[i];
            out[0] = s;
            g_rowsum = 0.0f;               // reset for next replay
            g_cnt2   = 0u;
        }
    }
}

extern "C" void kernel_launch(void* const* d_in, const int* in_sizes, int n_in,
                              void* d_out, int out_size) {
    const float* preds = (const float*)d_in[0];
    const float* targs = (const float*)d_in[1];
    float* out = (float*)d_out;

    dim3 gridM(CB_ITILES, CB_B);        // (32, 16) = 512 blocks x 256 thr
    chamfer_main<<<gridM, CB_TPB>>>(preds, targs, out);
}

// round 14
// speedup vs baseline: 1.1523x; 1.0012x over previous
#include <cuda_runtime.h>
#include <cuda_bf16.h>

// Chamfer distance, B=16, N=M=2048, D=3 — shared-pair kernel (R10 base).
// R10 structure verbatim (best measured: 25.1us). ONE tweak class vs R10:
// higher in-warp ILP in the hot loop — 4 row-min accumulators (chain depth
// 4 -> 2) and i-loop unrolled x2 so two independent iterations pipeline.
//
// Each unique (pred,targ) d^2 evaluated once; row mins (pred->targ) and col
// mins (targ->pred) reduced from the same packed f32x2 values.
// Rows: REDUX.MIN.U32 per warp -> smem -> block combine -> atomicAdd(g_rowsum).
// Cols: register mins -> atomicMax on order-REVERSED encoding (identity 0 =>
// zero-init scratch, reset by finalize -> graph-replay safe).

#define CB_NPTS   2048
#define CB_B      16
#define CB_TPB    256
#define CB_NW     (CB_TPB / 32)           // 8 warps
#define CB_TI     64                      // preds per block
#define CB_ITILES (CB_NPTS / CB_TI)       // 32
#define CB_PPL    4                       // packed target-pairs per lane

__device__ unsigned g_col[CB_B * CB_NPTS];  // encR col minima; 0 = identity
__device__ float    g_rowsum;               // zero-init; reset by finalize

__device__ __forceinline__ unsigned long long f32x2_fma(
    unsigned long long a, unsigned long long b, unsigned long long c) {
    unsigned long long d;
    asm("fma.rn.f32x2 %0, %1, %2, %3;" : "=l"(d) : "l"(a), "l"(b), "l"(c));
    return d;
}
__device__ __forceinline__ unsigned long long f32x2_add(
    unsigned long long a, unsigned long long b) {
    unsigned long long d;
    asm("add.rn.f32x2 %0, %1, %2;" : "=l"(d) : "l"(a), "l"(b));
    return d;
}
__device__ __forceinline__ void f32x2_unpack(unsigned long long v, float& lo, float& hi) {
    asm("mov.b64 {%0, %1}, %2;" : "=f"(lo), "=f"(hi) : "l"(v));
}
__device__ __forceinline__ unsigned long long f32x2_pack(float lo, float hi) {
    unsigned long long v;
    asm("mov.b64 %0, {%1, %2};" : "=l"(v) : "f"(lo), "f"(hi));
    return v;
}

// Order-PRESERVING encode (for REDUX.MIN): smaller float -> smaller code.
__device__ __forceinline__ unsigned encP(float f) {
    unsigned u = __float_as_uint(f);
    unsigned m = (unsigned)(((int)u) >> 31) | 0x80000000u;
    return u ^ m;
}
__device__ __forceinline__ float decP(unsigned e) {
    unsigned m = (~(unsigned)(((int)e) >> 31)) | 0x80000000u;
    return __uint_as_float(e ^ m);
}
// Order-REVERSED encode (for atomicMax with zero identity).
__device__ __forceinline__ unsigned encR(float f) { return ~encP(f); }
__device__ __forceinline__ float decR(unsigned r) { return decP(~r); }

__global__ __launch_bounds__(CB_TPB)
void chamfer_main(const float* __restrict__ preds,
                  const float* __restrict__ targs,
                  float* __restrict__ out)
{
    __shared__ unsigned long long sPack[1024 * 4];  // packed targ pairs (32KB)
    __shared__ float4   sQ[CB_TI];                  // (x0,x1,x2,|x|^2)
    __shared__ unsigned sRowE[CB_TI * CB_NW];       // per-warp encoded row mins

    const int b   = blockIdx.y;
    const int tid = threadIdx.x;
    const int wid = tid >> 5;
    const int ln  = tid & 31;

    if (blockIdx.x == 0 && blockIdx.y == 0 && tid == 0)
        out[0] = 0.0f;    // finalize runs after us in stream order

    // ---- stage ALL 2048 targets as packed, pre-scaled pairs ----
    const float* tB = targs + (size_t)b * CB_NPTS * 3;
    for (int pp = tid; pp < 1024; pp += CB_TPB) {
        const float* r = tB + pp * 6;
        float a0 = r[0], a1 = r[1], a2 = r[2];
        float c0 = r[3], c1 = r[4], c2 = r[5];
        sPack[pp * 4 + 0] = f32x2_pack(-2.0f * a0, -2.0f * c0);
        sPack[pp * 4 + 1] = f32x2_pack(-2.0f * a1, -2.0f * c1);
        sPack[pp * 4 + 2] = f32x2_pack(-2.0f * a2, -2.0f * c2);
        sPack[pp * 4 + 3] = f32x2_pack(fmaf(a0, a0, fmaf(a1, a1, a2 * a2)),
                                       fmaf(c0, c0, fmaf(c1, c1, c2 * c2)));
    }
    // ---- stage this block's 64 preds with |x|^2 ----
    const float* pB = preds + (size_t)b * CB_NPTS * 3;
    if (tid < CB_TI) {
        int i = blockIdx.x * CB_TI + tid;
        float x0 = pB[i * 3 + 0];
        float x1 = pB[i * 3 + 1];
        float x2 = pB[i * 3 + 2];
        sQ[tid] = make_float4(x0, x1, x2, fmaf(x0, x0, fmaf(x1, x1, x2 * x2)));
    }
    __syncthreads();

    // ---- pull this lane's 4 packed target pairs into registers ----
    unsigned long long rax[CB_PPL], ray[CB_PPL], rbx[CB_PPL], rby[CB_PPL];
    #pragma unroll
    for (int r = 0; r < CB_PPL; ++r) {
        int pp = wid * (32 * CB_PPL) + r * 32 + ln;
        rax[r] = sPack[pp * 4 + 0];
        ray[r] = sPack[pp * 4 + 1];
        rbx[r] = sPack[pp * 4 + 2];
        rby[r] = sPack[pp * 4 + 3];
    }

    float cmin[2 * CB_PPL];
    #pragma unroll
    for (int r = 0; r < 2 * CB_PPL; ++r) cmin[r] = 3.402823466e38f;

    // ---- main loop: 64 preds x 8 lane-targets, 2 iters pipelined ----
    #pragma unroll 2
    for (int i = 0; i < CB_TI; ++i) {
        float4 q = sQ[i];                                   // LDS.128 broadcast
        unsigned long long q0  = f32x2_pack(q.x, q.x);
        unsigned long long q1  = f32x2_pack(q.y, q.y);
        unsigned long long q2  = f32x2_pack(q.z, q.z);
        unsigned long long xxp = f32x2_pack(q.w, q.w);

        // 4 independent row-min accumulators (chain depth 2 instead of 4)
        float rma = 3.402823466e38f, rmb = 3.402823466e38f;
        float rmc = 3.402823466e38f, rmd = 3.402823466e38f;
        #pragma unroll
        for (int r = 0; r < CB_PPL; ++r) {
            unsigned long long t = f32x2_fma(q2, rbx[r], rby[r]);
            t = f32x2_fma(q1, ray[r], t);
            t = f32x2_fma(q0, rax[r], t);               // t = yy - 2 x.y
            unsigned long long u = f32x2_add(t, xxp);   // u = d^2
            float tl, th, ul, uh;
            f32x2_unpack(t, tl, th);
            f32x2_unpack(u, ul, uh);
            if (r & 1) { rmc = fminf(rmc, tl); rmd = fminf(rmd, th); }
            else       { rma = fminf(rma, tl); rmb = fminf(rmb, th); }
            cmin[2 * r]     = fminf(cmin[2 * r],     ul);
            cmin[2 * r + 1] = fminf(cmin[2 * r + 1], uh);
        }
        unsigned e = encP(fminf(fminf(rma, rmb), fminf(rmc, rmd)));
        e = __reduce_min_sync(0xffffffffu, e);          // REDUX.MIN.U32
        if (ln == 0) sRowE[i * CB_NW + wid] = e;
    }

    // ---- publish col minima (REDG.MAX on reversed encoding) ----
    unsigned* gc = g_col + (size_t)b * CB_NPTS;
    #pragma unroll
    for (int r = 0; r < CB_PPL; ++r) {
        int pp = wid * (32 * CB_PPL) + r * 32 + ln;
        atomicMax(&gc[2 * pp],     encR(cmin[2 * r]));
        atomicMax(&gc[2 * pp + 1], encR(cmin[2 * r + 1]));
    }

    __syncthreads();

    // ---- row side: combine 8 warps, add |x|^2, sum, one atomic per warp ----
    if (tid < CB_TI) {
        const unsigned* e = &sRowE[tid * CB_NW];
        unsigned m01 = min(e[0], e[1]), m23 = min(e[2], e[3]);
        unsigned m45 = min(e[4], e[5]), m67 = min(e[6], e[7]);
        unsigned em = min(min(m01, m23), min(m45, m67));
        float val = sQ[tid].w + decP(em);
        #pragma unroll
        for (int o = 16; o > 0; o >>= 1)
            val += __shfl_down_sync(0xffffffffu, val, o);
        if (ln == 0) atomicAdd(&g_rowsum, val);
    }
}

__global__ __launch_bounds__(128)
void chamfer_finalize(float* __restrict__ out)
{
    __shared__ float sRed[4];
    const int b = blockIdx.y;
    const int j = blockIdx.x * 128 + threadIdx.x;   // 16 blocks per batch
    unsigned* gc = g_col + (size_t)b * CB_NPTS;

    float acc = decR(gc[j]);
    gc[j] = 0u;                          // reset identity for next replay

    #pragma unroll
    for (int o = 16; o > 0; o >>= 1)
        acc += __shfl_down_sync(0xffffffffu, acc, o);
    if ((threadIdx.x & 31) == 0) sRed[threadIdx.x >> 5] = acc;
    __syncthreads();
    if (threadIdx.x == 0) {
        float v2 = sRed[0] + sRed[1] + sRed[2] + sRed[3];
        if (blockIdx.x == 0 && blockIdx.y == 0) {
            v2 += g_rowsum;              // consume row-side sum
            g_rowsum = 0.0f;             // reset for next replay
        }
        atomicAdd(out, v2);
    }
}

extern "C" void kernel_launch(void* const* d_in, const int* in_sizes, int n_in,
                              void* d_out, int out_size) {
    const float* preds = (const float*)d_in[0];
    const float* targs = (const float*)d_in[1];
    float* out = (float*)d_out;

    dim3 gridM(CB_ITILES, CB_B);        // (32, 16) = 512 blocks x 256 thr
    chamfer_main<<<gridM, CB_TPB>>>(preds, targs, out);

    dim3 gridF(CB_NPTS / 128, CB_B);    // (16, 16) = 256 blocks x 128 thr
    chamfer_finalize<<<gridF, 128>>>(out);
}

// round 15
// speedup vs baseline: 1.2124x; 1.0522x over previous
#include <cuda_runtime.h>
#include <cuda_bf16.h>

// Chamfer distance, B=16, N=M=2048, D=3 — shared-pair kernel (R10 base).
// Hot loop, encodings, finalize: byte-identical to R10 (best: 25.1us).
// ONE change: pred tile TI 64 -> 32 (grid 512 -> 1024 blocks) so SMs run
// 4 resident blocks (32 warps/SM) instead of 3.46 — pure occupancy lever
// against the measured issue=49% latency stalls.
//
// Each unique (pred,targ) d^2 evaluated once; row mins (pred->targ) and col
// mins (targ->pred) reduced from the same packed f32x2 values.
// Rows: REDUX.MIN.U32 per warp -> smem -> block combine -> atomicAdd(g_rowsum).
// Cols: register mins -> atomicMax on order-REVERSED encoding (identity 0 =>
// zero-init scratch, reset by finalize -> graph-replay safe).

#define CB_NPTS   2048
#define CB_B      16
#define CB_TPB    256
#define CB_NW     (CB_TPB / 32)           // 8 warps
#define CB_TI     32                      // preds per block (was 64)
#define CB_ITILES (CB_NPTS / CB_TI)       // 64
#define CB_PPL    4                       // packed target-pairs per lane

__device__ unsigned g_col[CB_B * CB_NPTS];  // encR col minima; 0 = identity
__device__ float    g_rowsum;               // zero-init; reset by finalize

__device__ __forceinline__ unsigned long long f32x2_fma(
    unsigned long long a, unsigned long long b, unsigned long long c) {
    unsigned long long d;
    asm("fma.rn.f32x2 %0, %1, %2, %3;" : "=l"(d) : "l"(a), "l"(b), "l"(c));
    return d;
}
__device__ __forceinline__ unsigned long long f32x2_add(
    unsigned long long a, unsigned long long b) {
    unsigned long long d;
    asm("add.rn.f32x2 %0, %1, %2;" : "=l"(d) : "l"(a), "l"(b));
    return d;
}
__device__ __forceinline__ void f32x2_unpack(unsigned long long v, float& lo, float& hi) {
    asm("mov.b64 {%0, %1}, %2;" : "=f"(lo), "=f"(hi) : "l"(v));
}
__device__ __forceinline__ unsigned long long f32x2_pack(float lo, float hi) {
    unsigned long long v;
    asm("mov.b64 %0, {%1, %2};" : "=l"(v) : "f"(lo), "f"(hi));
    return v;
}

// Order-PRESERVING encode (for REDUX.MIN): smaller float -> smaller code.
__device__ __forceinline__ unsigned encP(float f) {
    unsigned u = __float_as_uint(f);
    unsigned m = (unsigned)(((int)u) >> 31) | 0x80000000u;
    return u ^ m;
}
__device__ __forceinline__ float decP(unsigned e) {
    unsigned m = (~(unsigned)(((int)e) >> 31)) | 0x80000000u;
    return __uint_as_float(e ^ m);
}
// Order-REVERSED encode (for atomicMax with zero identity).
__device__ __forceinline__ unsigned encR(float f) { return ~encP(f); }
__device__ __forceinline__ float decR(unsigned r) { return decP(~r); }

__global__ __launch_bounds__(CB_TPB)
void chamfer_main(const float* __restrict__ preds,
                  const float* __restrict__ targs,
                  float* __restrict__ out)
{
    __shared__ unsigned long long sPack[1024 * 4];  // packed targ pairs (32KB)
    __shared__ float4   sQ[CB_TI];                  // (x0,x1,x2,|x|^2)
    __shared__ unsigned sRowE[CB_TI * CB_NW];       // per-warp encoded row mins

    const int b   = blockIdx.y;
    const int tid = threadIdx.x;
    const int wid = tid >> 5;
    const int ln  = tid & 31;

    if (blockIdx.x == 0 && blockIdx.y == 0 && tid == 0)
        out[0] = 0.0f;    // finalize runs after us in stream order

    // ---- stage ALL 2048 targets as packed, pre-scaled pairs ----
    const float* tB = targs + (size_t)b * CB_NPTS * 3;
    for (int pp = tid; pp < 1024; pp += CB_TPB) {
        const float* r = tB + pp * 6;
        float a0 = r[0], a1 = r[1], a2 = r[2];
        float c0 = r[3], c1 = r[4], c2 = r[5];
        sPack[pp * 4 + 0] = f32x2_pack(-2.0f * a0, -2.0f * c0);
        sPack[pp * 4 + 1] = f32x2_pack(-2.0f * a1, -2.0f * c1);
        sPack[pp * 4 + 2] = f32x2_pack(-2.0f * a2, -2.0f * c2);
        sPack[pp * 4 + 3] = f32x2_pack(fmaf(a0, a0, fmaf(a1, a1, a2 * a2)),
                                       fmaf(c0, c0, fmaf(c1, c1, c2 * c2)));
    }
    // ---- stage this block's 32 preds with |x|^2 ----
    const float* pB = preds + (size_t)b * CB_NPTS * 3;
    if (tid < CB_TI) {
        int i = blockIdx.x * CB_TI + tid;
        float x0 = pB[i * 3 + 0];
        float x1 = pB[i * 3 + 1];
        float x2 = pB[i * 3 + 2];
        sQ[tid] = make_float4(x0, x1, x2, fmaf(x0, x0, fmaf(x1, x1, x2 * x2)));
    }
    __syncthreads();

    // ---- pull this lane's 4 packed target pairs into registers ----
    unsigned long long rax[CB_PPL], ray[CB_PPL], rbx[CB_PPL], rby[CB_PPL];
    #pragma unroll
    for (int r = 0; r < CB_PPL; ++r) {
        int pp = wid * (32 * CB_PPL) + r * 32 + ln;
        rax[r] = sPack[pp * 4 + 0];
        ray[r] = sPack[pp * 4 + 1];
        rbx[r] = sPack[pp * 4 + 2];
        rby[r] = sPack[pp * 4 + 3];
    }

    float cmin[2 * CB_PPL];
    #pragma unroll
    for (int r = 0; r < 2 * CB_PPL; ++r) cmin[r] = 3.402823466e38f;

    // ---- main loop: 32 preds x 8 lane-targets (EXACT R10 body) ----
    for (int i = 0; i < CB_TI; ++i) {
        float4 q = sQ[i];                                   // LDS.128 broadcast
        unsigned long long q0  = f32x2_pack(q.x, q.x);
        unsigned long long q1  = f32x2_pack(q.y, q.y);
        unsigned long long q2  = f32x2_pack(q.z, q.z);
        unsigned long long xxp = f32x2_pack(q.w, q.w);

        float rm0 = 3.402823466e38f, rm1 = 3.402823466e38f;
        #pragma unroll
        for (int r = 0; r < CB_PPL; ++r) {
            unsigned long long t = f32x2_fma(q2, rbx[r], rby[r]);
            t = f32x2_fma(q1, ray[r], t);
            t = f32x2_fma(q0, rax[r], t);               // t = yy - 2 x.y
            unsigned long long u = f32x2_add(t, xxp);   // u = d^2
            float tl, th, ul, uh;
            f32x2_unpack(t, tl, th);
            f32x2_unpack(u, ul, uh);
            rm0 = fminf(rm0, tl);
            rm1 = fminf(rm1, th);
            cmin[2 * r]     = fminf(cmin[2 * r],     ul);
            cmin[2 * r + 1] = fminf(cmin[2 * r + 1], uh);
        }
        unsigned e = encP(fminf(rm0, rm1));
        e = __reduce_min_sync(0xffffffffu, e);          // REDUX.MIN.U32
        if (ln == 0) sRowE[i * CB_NW + wid] = e;
    }

    // ---- publish col minima (REDG.MAX on reversed encoding) ----
    unsigned* gc = g_col + (size_t)b * CB_NPTS;
    #pragma unroll
    for (int r = 0; r < CB_PPL; ++r) {
        int pp = wid * (32 * CB_PPL) + r * 32 + ln;
        atomicMax(&gc[2 * pp],     encR(cmin[2 * r]));
        atomicMax(&gc[2 * pp + 1], encR(cmin[2 * r + 1]));
    }

    __syncthreads();

    // ---- row side: combine 8 warps, add |x|^2, sum, one atomic per warp ----
    if (tid < CB_TI) {
        const unsigned* e = &sRowE[tid * CB_NW];
        unsigned m01 = min(e[0], e[1]), m23 = min(e[2], e[3]);
        unsigned m45 = min(e[4], e[5]), m67 = min(e[6], e[7]);
        unsigned em = min(min(m01, m23), min(m45, m67));
        float val = sQ[tid].w + decP(em);
        #pragma unroll
        for (int o = 16; o > 0; o >>= 1)
            val += __shfl_down_sync(0xffffffffu, val, o);
        if (ln == 0) atomicAdd(&g_rowsum, val);
    }
}

__global__ __launch_bounds__(128)
void chamfer_finalize(float* __restrict__ out)
{
    __shared__ float sRed[4];
    const int b = blockIdx.y;
    const int j = blockIdx.x * 128 + threadIdx.x;   // 16 blocks per batch
    unsigned* gc = g_col + (size_t)b * CB_NPTS;

    float acc = decR(gc[j]);
    gc[j] = 0u;                          // reset identity for next replay

    #pragma unroll
    for (int o = 16; o > 0; o >>= 1)
        acc += __shfl_down_sync(0xffffffffu, acc, o);
    if ((threadIdx.x & 31) == 0) sRed[threadIdx.x >> 5] = acc;
    __syncthreads();
    if (threadIdx.x == 0) {
        float v2 = sRed[0] + sRed[1] + sRed[2] + sRed[3];
        if (blockIdx.x == 0 && blockIdx.y == 0) {
            v2 += g_rowsum;              // consume row-side sum
            g_rowsum = 0.0f;             // reset for next replay
        }
        atomicAdd(out, v2);
    }
}

extern "C" void kernel_launch(void* const* d_in, const int* in_sizes, int n_in,
                              void* d_out, int out_size) {
    const float* preds = (const float*)d_in[0];
    const float* targs = (const float*)d_in[1];
    float* out = (float*)d_out;

    dim3 gridM(CB_ITILES, CB_B);        // (64, 16) = 1024 blocks x 256 thr
    chamfer_main<<<gridM, CB_TPB>>>(preds, targs, out);

    dim3 gridF(CB_NPTS / 128, CB_B);    // (16, 16) = 256 blocks x 128 thr
    chamfer_finalize<<<gridF, 128>>>(out);
}

// round 16
// speedup vs baseline: 1.2323x; 1.0164x over previous
#include <cuda_runtime.h>
#include <cuda_bf16.h>

// Chamfer distance, B=16, N=M=2048, D=3 — shared-pair kernel.
// BOTH kernels byte-identical to R10 (best measured: 25.1us).
// ONE change: finalize launched with Programmatic Dependent Launch so its
// ~3.5us execution-overhead floor overlaps chamfer_main's drain; only the
// ~1us of real dependent work remains exposed after main completes.
//
// Each unique (pred,targ) d^2 evaluated once; row mins (pred->targ) and col
// mins (targ->pred) reduced from the same packed f32x2 values.
// Rows: REDUX.MIN.U32 per warp -> smem -> block combine -> atomicAdd(g_rowsum).
// Cols: register mins -> atomicMax on order-REVERSED encoding (identity 0 =>
// zero-init scratch, reset by finalize -> graph-replay safe).

#define CB_NPTS   2048
#define CB_B      16
#define CB_TPB    256
#define CB_NW     (CB_TPB / 32)           // 8 warps
#define CB_TI     64                      // preds per block
#define CB_ITILES (CB_NPTS / CB_TI)       // 32
#define CB_PPL    4                       // packed target-pairs per lane

__device__ unsigned g_col[CB_B * CB_NPTS];  // encR col minima; 0 = identity
__device__ float    g_rowsum;               // zero-init; reset by finalize

__device__ __forceinline__ unsigned long long f32x2_fma(
    unsigned long long a, unsigned long long b, unsigned long long c) {
    unsigned long long d;
    asm("fma.rn.f32x2 %0, %1, %2, %3;" : "=l"(d) : "l"(a), "l"(b), "l"(c));
    return d;
}
__device__ __forceinline__ unsigned long long f32x2_add(
    unsigned long long a, unsigned long long b) {
    unsigned long long d;
    asm("add.rn.f32x2 %0, %1, %2;" : "=l"(d) : "l"(a), "l"(b));
    return d;
}
__device__ __forceinline__ void f32x2_unpack(unsigned long long v, float& lo, float& hi) {
    asm("mov.b64 {%0, %1}, %2;" : "=f"(lo), "=f"(hi) : "l"(v));
}
__device__ __forceinline__ unsigned long long f32x2_pack(float lo, float hi) {
    unsigned long long v;
    asm("mov.b64 %0, {%1, %2};" : "=l"(v) : "f"(lo), "f"(hi));
    return v;
}

// Order-PRESERVING encode (for REDUX.MIN): smaller float -> smaller code.
__device__ __forceinline__ unsigned encP(float f) {
    unsigned u = __float_as_uint(f);
    unsigned m = (unsigned)(((int)u) >> 31) | 0x80000000u;
    return u ^ m;
}
__device__ __forceinline__ float decP(unsigned e) {
    unsigned m = (~(unsigned)(((int)e) >> 31)) | 0x80000000u;
    return __uint_as_float(e ^ m);
}
// Order-REVERSED encode (for atomicMax with zero identity).
__device__ __forceinline__ unsigned encR(float f) { return ~encP(f); }
__device__ __forceinline__ float decR(unsigned r) { return decP(~r); }

__global__ __launch_bounds__(CB_TPB)
void chamfer_main(const float* __restrict__ preds,
                  const float* __restrict__ targs,
                  float* __restrict__ out)
{
    __shared__ unsigned long long sPack[1024 * 4];  // packed targ pairs (32KB)
    __shared__ float4   sQ[CB_TI];                  // (x0,x1,x2,|x|^2)
    __shared__ unsigned sRowE[CB_TI * CB_NW];       // per-warp encoded row mins

    const int b   = blockIdx.y;
    const int tid = threadIdx.x;
    const int wid = tid >> 5;
    const int ln  = tid & 31;

    if (blockIdx.x == 0 && blockIdx.y == 0 && tid == 0)
        out[0] = 0.0f;    // visible to finalize via PDL grid-dependency sync

    // ---- stage ALL 2048 targets as packed, pre-scaled pairs ----
    const float* tB = targs + (size_t)b * CB_NPTS * 3;
    for (int pp = tid; pp < 1024; pp += CB_TPB) {
        const float* r = tB + pp * 6;
        float a0 = r[0], a1 = r[1], a2 = r[2];
        float c0 = r[3], c1 = r[4], c2 = r[5];
        sPack[pp * 4 + 0] = f32x2_pack(-2.0f * a0, -2.0f * c0);
        sPack[pp * 4 + 1] = f32x2_pack(-2.0f * a1, -2.0f * c1);
        sPack[pp * 4 + 2] = f32x2_pack(-2.0f * a2, -2.0f * c2);
        sPack[pp * 4 + 3] = f32x2_pack(fmaf(a0, a0, fmaf(a1, a1, a2 * a2)),
                                       fmaf(c0, c0, fmaf(c1, c1, c2 * c2)));
    }
    // ---- stage this block's 64 preds with |x|^2 ----
    const float* pB = preds + (size_t)b * CB_NPTS * 3;
    if (tid < CB_TI) {
        int i = blockIdx.x * CB_TI + tid;
        float x0 = pB[i * 3 + 0];
        float x1 = pB[i * 3 + 1];
        float x2 = pB[i * 3 + 2];
        sQ[tid] = make_float4(x0, x1, x2, fmaf(x0, x0, fmaf(x1, x1, x2 * x2)));
    }
    __syncthreads();

    // ---- pull this lane's 4 packed target pairs into registers ----
    unsigned long long rax[CB_PPL], ray[CB_PPL], rbx[CB_PPL], rby[CB_PPL];
    #pragma unroll
    for (int r = 0; r < CB_PPL; ++r) {
        int pp = wid * (32 * CB_PPL) + r * 32 + ln;
        rax[r] = sPack[pp * 4 + 0];
        ray[r] = sPack[pp * 4 + 1];
        rbx[r] = sPack[pp * 4 + 2];
        rby[r] = sPack[pp * 4 + 3];
    }

    float cmin[2 * CB_PPL];
    #pragma unroll
    for (int r = 0; r < 2 * CB_PPL; ++r) cmin[r] = 3.402823466e38f;

    // ---- main loop: 64 preds x 8 lane-targets (EXACT R10 body) ----
    for (int i = 0; i < CB_TI; ++i) {
        float4 q = sQ[i];                                   // LDS.128 broadcast
        unsigned long long q0  = f32x2_pack(q.x, q.x);
        unsigned long long q1  = f32x2_pack(q.y, q.y);
        unsigned long long q2  = f32x2_pack(q.z, q.z);
        unsigned long long xxp = f32x2_pack(q.w, q.w);

        float rm0 = 3.402823466e38f, rm1 = 3.402823466e38f;
        #pragma unroll
        for (int r = 0; r < CB_PPL; ++r) {
            unsigned long long t = f32x2_fma(q2, rbx[r], rby[r]);
            t = f32x2_fma(q1, ray[r], t);
            t = f32x2_fma(q0, rax[r], t);               // t = yy - 2 x.y
            unsigned long long u = f32x2_add(t, xxp);   // u = d^2
            float tl, th, ul, uh;
            f32x2_unpack(t, tl, th);
            f32x2_unpack(u, ul, uh);
            rm0 = fminf(rm0, tl);
            rm1 = fminf(rm1, th);
            cmin[2 * r]     = fminf(cmin[2 * r],     ul);
            cmin[2 * r + 1] = fminf(cmin[2 * r + 1], uh);
        }
        unsigned e = encP(fminf(rm0, rm1));
        e = __reduce_min_sync(0xffffffffu, e);          // REDUX.MIN.U32
        if (ln == 0) sRowE[i * CB_NW + wid] = e;
    }

    // ---- publish col minima (REDG.MAX on reversed encoding) ----
    unsigned* gc = g_col + (size_t)b * CB_NPTS;
    #pragma unroll
    for (int r = 0; r < CB_PPL; ++r) {
        int pp = wid * (32 * CB_PPL) + r * 32 + ln;
        atomicMax(&gc[2 * pp],     encR(cmin[2 * r]));
        atomicMax(&gc[2 * pp + 1], encR(cmin[2 * r + 1]));
    }

    __syncthreads();

    // ---- row side: combine 8 warps, add |x|^2, sum, one atomic per warp ----
    if (tid < CB_TI) {
        const unsigned* e = &sRowE[tid * CB_NW];
        unsigned m01 = min(e[0], e[1]), m23 = min(e[2], e[3]);
        unsigned m45 = min(e[4], e[5]), m67 = min(e[6], e[7]);
        unsigned em = min(min(m01, m23), min(m45, m67));
        float val = sQ[tid].w + decP(em);
        #pragma unroll
        for (int o = 16; o > 0; o >>= 1)
            val += __shfl_down_sync(0xffffffffu, val, o);
        if (ln == 0) atomicAdd(&g_rowsum, val);
    }
}

__global__ __launch_bounds__(128)
void chamfer_finalize(float* __restrict__ out)
{
    // PDL: wait for chamfer_main's full completion (+ memory visibility).
    cudaGridDependencySynchronize();

    __shared__ float sRed[4];
    const int b = blockIdx.y;
    const int j = blockIdx.x * 128 + threadIdx.x;   // 16 blocks per batch
    unsigned* gc = g_col + (size_t)b * CB_NPTS;

    float acc = decR(gc[j]);
    gc[j] = 0u;                          // reset identity for next replay

    #pragma unroll
    for (int o = 16; o > 0; o >>= 1)
        acc += __shfl_down_sync(0xffffffffu, acc, o);
    if ((threadIdx.x & 31) == 0) sRed[threadIdx.x >> 5] = acc;
    __syncthreads();
    if (threadIdx.x == 0) {
        float v2 = sRed[0] + sRed[1] + sRed[2] + sRed[3];
        if (blockIdx.x == 0 && blockIdx.y == 0) {
            v2 += g_rowsum;              // consume row-side sum
            g_rowsum = 0.0f;             // reset for next replay
        }
        atomicAdd(out, v2);
    }
}

extern "C" void kernel_launch(void* const* d_in, const int* in_sizes, int n_in,
                              void* d_out, int out_size) {
    const float* preds = (const float*)d_in[0];
    const float* targs = (const float*)d_in[1];
    float* out = (float*)d_out;

    dim3 gridM(CB_ITILES, CB_B);        // (32, 16) = 512 blocks x 256 thr
    chamfer_main<<<gridM, CB_TPB>>>(preds, targs, out);

    // Finalize with Programmatic Dependent Launch: its launch/setup overhead
    // overlaps main's drain; cudaGridDependencySynchronize() inside provides
    // ordering + memory visibility.
    cudaLaunchConfig_t cfg = {};
    cfg.gridDim  = dim3(CB_NPTS / 128, CB_B);   // (16,16) = 256 blocks
    cfg.blockDim = dim3(128);
    cudaLaunchAttribute attrs[1];
    attrs[0].id = cudaLaunchAttributeProgrammaticStreamSerialization;
    attrs[0].val.programmaticStreamSerializationAllowed = 1;
    cfg.attrs = attrs;
    cfg.numAttrs = 1;
    cudaLaunchKernelEx(&cfg, chamfer_finalize, out);
}

// round 17
// speedup vs baseline: 1.2339x; 1.0013x over previous
#include <cuda_runtime.h>
#include <cuda_bf16.h>

// Chamfer distance, B=16, N=M=2048, D=3 — shared-pair kernel (R10 logic).
// ONE change vs R10 (best: 25.1us): amortization depth — TPB 256 -> 128 and
// PPL 4 -> 8, so each warp covers 512 targets and the per-iteration fixed
// overhead (8 q-broadcast MOVs + REDUX + encode + LDS) is halved per pair
// (instr/pair 0.168 -> 0.150), and total REDUX count halves. Hot-loop body,
// tiling (TI=64, grid 32x16), encodings, finalize: identical to R10.

#define CB_NPTS   2048
#define CB_B      16
#define CB_TPB    128
#define CB_NW     (CB_TPB / 32)           // 4 warps
#define CB_TI     64                      // preds per block
#define CB_ITILES (CB_NPTS / CB_TI)       // 32
#define CB_PPL    8                       // packed target-pairs per lane

__device__ unsigned g_col[CB_B * CB_NPTS];  // encR col minima; 0 = identity
__device__ float    g_rowsum;               // zero-init; reset by finalize

__device__ __forceinline__ unsigned long long f32x2_fma(
    unsigned long long a, unsigned long long b, unsigned long long c) {
    unsigned long long d;
    asm("fma.rn.f32x2 %0, %1, %2, %3;" : "=l"(d) : "l"(a), "l"(b), "l"(c));
    return d;
}
__device__ __forceinline__ unsigned long long f32x2_add(
    unsigned long long a, unsigned long long b) {
    unsigned long long d;
    asm("add.rn.f32x2 %0, %1, %2;" : "=l"(d) : "l"(a), "l"(b));
    return d;
}
__device__ __forceinline__ void f32x2_unpack(unsigned long long v, float& lo, float& hi) {
    asm("mov.b64 {%0, %1}, %2;" : "=f"(lo), "=f"(hi) : "l"(v));
}
__device__ __forceinline__ unsigned long long f32x2_pack(float lo, float hi) {
    unsigned long long v;
    asm("mov.b64 %0, {%1, %2};" : "=l"(v) : "f"(lo), "f"(hi));
    return v;
}

// Order-PRESERVING encode (for REDUX.MIN): smaller float -> smaller code.
__device__ __forceinline__ unsigned encP(float f) {
    unsigned u = __float_as_uint(f);
    unsigned m = (unsigned)(((int)u) >> 31) | 0x80000000u;
    return u ^ m;
}
__device__ __forceinline__ float decP(unsigned e) {
    unsigned m = (~(unsigned)(((int)e) >> 31)) | 0x80000000u;
    return __uint_as_float(e ^ m);
}
// Order-REVERSED encode (for atomicMax with zero identity).
__device__ __forceinline__ unsigned encR(float f) { return ~encP(f); }
__device__ __forceinline__ float decR(unsigned r) { return decP(~r); }

__global__ __launch_bounds__(CB_TPB)
void chamfer_main(const float* __restrict__ preds,
                  const float* __restrict__ targs,
                  float* __restrict__ out)
{
    __shared__ unsigned long long sPack[1024 * 4];  // packed targ pairs (32KB)
    __shared__ float4   sQ[CB_TI];                  // (x0,x1,x2,|x|^2)
    __shared__ unsigned sRowE[CB_TI * CB_NW];       // per-warp encoded row mins

    const int b   = blockIdx.y;
    const int tid = threadIdx.x;
    const int wid = tid >> 5;
    const int ln  = tid & 31;

    if (blockIdx.x == 0 && blockIdx.y == 0 && tid == 0)
        out[0] = 0.0f;    // finalize runs after us in stream order

    // ---- stage ALL 2048 targets as packed, pre-scaled pairs ----
    const float* tB = targs + (size_t)b * CB_NPTS * 3;
    for (int pp = tid; pp < 1024; pp += CB_TPB) {
        const float* r = tB + pp * 6;
        float a0 = r[0], a1 = r[1], a2 = r[2];
        float c0 = r[3], c1 = r[4], c2 = r[5];
        sPack[pp * 4 + 0] = f32x2_pack(-2.0f * a0, -2.0f * c0);
        sPack[pp * 4 + 1] = f32x2_pack(-2.0f * a1, -2.0f * c1);
        sPack[pp * 4 + 2] = f32x2_pack(-2.0f * a2, -2.0f * c2);
        sPack[pp * 4 + 3] = f32x2_pack(fmaf(a0, a0, fmaf(a1, a1, a2 * a2)),
                                       fmaf(c0, c0, fmaf(c1, c1, c2 * c2)));
    }
    // ---- stage this block's 64 preds with |x|^2 ----
    const float* pB = preds + (size_t)b * CB_NPTS * 3;
    if (tid < CB_TI) {
        int i = blockIdx.x * CB_TI + tid;
        float x0 = pB[i * 3 + 0];
        float x1 = pB[i * 3 + 1];
        float x2 = pB[i * 3 + 2];
        sQ[tid] = make_float4(x0, x1, x2, fmaf(x0, x0, fmaf(x1, x1, x2 * x2)));
    }
    __syncthreads();

    // ---- pull this lane's 8 packed target pairs into registers ----
    unsigned long long rax[CB_PPL], ray[CB_PPL], rbx[CB_PPL], rby[CB_PPL];
    #pragma unroll
    for (int r = 0; r < CB_PPL; ++r) {
        int pp = wid * (32 * CB_PPL) + r * 32 + ln;
        rax[r] = sPack[pp * 4 + 0];
        ray[r] = sPack[pp * 4 + 1];
        rbx[r] = sPack[pp * 4 + 2];
        rby[r] = sPack[pp * 4 + 3];
    }

    float cmin[2 * CB_PPL];
    #pragma unroll
    for (int r = 0; r < 2 * CB_PPL; ++r) cmin[r] = 3.402823466e38f;

    // ---- main loop: 64 preds x 16 lane-targets (R10 body, wider r) ----
    for (int i = 0; i < CB_TI; ++i) {
        float4 q = sQ[i];                                   // LDS.128 broadcast
        unsigned long long q0  = f32x2_pack(q.x, q.x);
        unsigned long long q1  = f32x2_pack(q.y, q.y);
        unsigned long long q2  = f32x2_pack(q.z, q.z);
        unsigned long long xxp = f32x2_pack(q.w, q.w);

        float rm0 = 3.402823466e38f, rm1 = 3.402823466e38f;
        #pragma unroll
        for (int r = 0; r < CB_PPL; ++r) {
            unsigned long long t = f32x2_fma(q2, rbx[r], rby[r]);
            t = f32x2_fma(q1, ray[r], t);
            t = f32x2_fma(q0, rax[r], t);               // t = yy - 2 x.y
            unsigned long long u = f32x2_add(t, xxp);   // u = d^2
            float tl, th, ul, uh;
            f32x2_unpack(t, tl, th);
            f32x2_unpack(u, ul, uh);
            rm0 = fminf(rm0, tl);
            rm1 = fminf(rm1, th);
            cmin[2 * r]     = fminf(cmin[2 * r],     ul);
            cmin[2 * r + 1] = fminf(cmin[2 * r + 1], uh);
        }
        unsigned e = encP(fminf(rm0, rm1));
        e = __reduce_min_sync(0xffffffffu, e);          // REDUX.MIN.U32
        if (ln == 0) sRowE[i * CB_NW + wid] = e;
    }

    // ---- publish col minima (REDG.MAX on reversed encoding) ----
    unsigned* gc = g_col + (size_t)b * CB_NPTS;
    #pragma unroll
    for (int r = 0; r < CB_PPL; ++r) {
        int pp = wid * (32 * CB_PPL) + r * 32 + ln;
        atomicMax(&gc[2 * pp],     encR(cmin[2 * r]));
        atomicMax(&gc[2 * pp + 1], encR(cmin[2 * r + 1]));
    }

    __syncthreads();

    // ---- row side: combine 4 warps, add |x|^2, sum, one atomic per warp ----
    if (tid < CB_TI) {
        const unsigned* e = &sRowE[tid * CB_NW];
        unsigned em = min(min(e[0], e[1]), min(e[2], e[3]));
        float val = sQ[tid].w + decP(em);
        #pragma unroll
        for (int o = 16; o > 0; o >>= 1)
            val += __shfl_down_sync(0xffffffffu, val, o);
        if (ln == 0) atomicAdd(&g_rowsum, val);
    }
}

__global__ __launch_bounds__(128)
void chamfer_finalize(float* __restrict__ out)
{
    __shared__ float sRed[4];
    const int b = blockIdx.y;
    const int j = blockIdx.x * 128 + threadIdx.x;   // 16 blocks per batch
    unsigned* gc = g_col + (size_t)b * CB_NPTS;

    float acc = decR(gc[j]);
    gc[j] = 0u;                          // reset identity for next replay

    #pragma unroll
    for (int o = 16; o > 0; o >>= 1)
        acc += __shfl_down_sync(0xffffffffu, acc, o);
    if ((threadIdx.x & 31) == 0) sRed[threadIdx.x >> 5] = acc;
    __syncthreads();
    if (threadIdx.x == 0) {
        float v2 = sRed[0] + sRed[1] + sRed[2] + sRed[3];
        if (blockIdx.x == 0 && blockIdx.y == 0) {
            v2 += g_rowsum;              // consume row-side sum
            g_rowsum = 0.0f;             // reset for next replay
        }
        atomicAdd(out, v2);
    }
}

extern "C" void kernel_launch(void* const* d_in, const int* in_sizes, int n_in,
                              void* d_out, int out_size) {
    const float* preds = (const float*)d_in[0];
    const float* targs = (const float*)d_in[1];
    float* out = (float*)d_out;

    dim3 gridM(CB_ITILES, CB_B);        // (32, 16) = 512 blocks x 128 thr
    chamfer_main<<<gridM, CB_TPB>>>(preds, targs, out);

    dim3 gridF(CB_NPTS / 128, CB_B);    // (16, 16) = 256 blocks x 128 thr
    chamfer_finalize<<<gridF, 128>>>(out);
}